// round 1
// baseline (speedup 1.0000x reference)
#include <cuda_runtime.h>
#include <math.h>
#include <math_constants.h>

#define BB 2
#define TT 2048
#define SS 2048
#define DD 256
#define HH 8
#define DHH 32
#define FFD 2048
#define VOC 25426
#define BT (BB*TT)

// ---------------- scratch (no allocations allowed) ----------------
// Layout (float offsets, each x0..encz slab is BT*DD = 1048576 floats):
#define SLAB 1048576
#define O_X0   (0*SLAB)
#define O_X1   (1*SLAB)
#define O_X2   (2*SLAB)
#define O_X3   (3*SLAB)
#define O_Q    (4*SLAB)
#define O_K    (5*SLAB)
#define O_V    (6*SLAB)
#define O_ATT  (7*SLAB)
#define O_PROJ (8*SLAB)
#define O_ENCZ (9*SLAB)
#define O_FF   (10*SLAB)              // BT*FFD = 8388608 floats
#define SCRATCH_FLOATS (18*SLAB)

__device__ float g_scratch[SCRATCH_FLOATS];
__device__ float g_padbuf[BT];        // tgt padding mask (1.0 if id != 0)

// ---------------- embedding + positional encoding ----------------
// x = emb[tgt]; x = x + (x + pe)  ==  2*emb[tgt] + pe
__global__ void k_embed(const int* __restrict__ tgt_in,
                        const float* __restrict__ emb,
                        float* __restrict__ out_ids, int write_ids)
{
    int r = blockIdx.x;          // b*TT + t
    int d = threadIdx.x;         // 0..255
    int b = r / TT, t = r % TT;
    int id = (t == 0) ? VOC : tgt_in[b*(TT-1) + (t-1)];
    if (d == 0) {
        g_padbuf[r] = (id != 0) ? 1.0f : 0.0f;
        if (write_ids) out_ids[r] = (t == 0) ? 0.0f : (float)id;
    }
    int i2 = d & ~1;             // 2*(d/2)
    float div = __expf(-(float)i2 * (9.210340371976184f / 256.0f));
    float ang = (float)t * div;
    float pe  = (d & 1) ? cosf(ang) : sinf(ang);
    g_scratch[O_X0 + (size_t)r*DD + d] = 2.0f*emb[(size_t)id*DD + d] + pe;
}

// enc = where(src_input_id != 0, enc_in, 0)
__global__ void k_encz(const int* __restrict__ src, const float* __restrict__ enc)
{
    int r = blockIdx.x;          // b*SS + s
    int d = threadIdx.x;
    g_scratch[O_ENCZ + (size_t)r*DD + d] = (src[r] != 0) ? enc[(size_t)r*DD + d] : 0.0f;
}

// ---------------- generic SGEMM: C[M,N] = A[M,K] @ B[K,N] (+bias)(+gelu) ----
// 64x64 tile, BK=16, 16x16 threads, 4x4 micro-tile, float4 shared reads.
// M multiple of 64, K multiple of 16 (guaranteed). N guarded.
__global__ void __launch_bounds__(256)
k_gemm(const float* __restrict__ A, const float* __restrict__ Bm,
       const float* __restrict__ bias, float* __restrict__ C,
       int M, int N, int K, int act)
{
    __shared__ float As[16][64];
    __shared__ float Bs[16][64];
    int tx = threadIdx.x, ty = threadIdx.y;
    int lin = ty*16 + tx;
    int n0 = blockIdx.x*64, m0 = blockIdx.y*64;

    float acc[4][4] = {};
    int am = lin >> 2;                 // 0..63
    int ak = (lin & 3) * 4;            // 0,4,8,12
    int bk = lin >> 4;                 // 0..15
    int bn = (lin & 15) * 4;           // 0..60

    for (int k0 = 0; k0 < K; k0 += 16) {
        float4 av = *(const float4*)&A[(size_t)(m0+am)*K + k0 + ak];
        As[ak+0][am] = av.x; As[ak+1][am] = av.y;
        As[ak+2][am] = av.z; As[ak+3][am] = av.w;
        #pragma unroll
        for (int j = 0; j < 4; j++) {
            int n = n0 + bn + j;
            Bs[bk][bn+j] = (n < N) ? Bm[(size_t)(k0+bk)*N + n] : 0.0f;
        }
        __syncthreads();
        #pragma unroll
        for (int kk = 0; kk < 16; kk++) {
            float4 a = *(const float4*)&As[kk][ty*4];
            float4 b = *(const float4*)&Bs[kk][tx*4];
            float ar[4] = {a.x, a.y, a.z, a.w};
            float br[4] = {b.x, b.y, b.z, b.w};
            #pragma unroll
            for (int i = 0; i < 4; i++)
                #pragma unroll
                for (int j = 0; j < 4; j++)
                    acc[i][j] += ar[i]*br[j];
        }
        __syncthreads();
    }
    #pragma unroll
    for (int i = 0; i < 4; i++) {
        int m = m0 + ty*4 + i;
        #pragma unroll
        for (int j = 0; j < 4; j++) {
            int n = n0 + tx*4 + j;
            if (n < N) {
                float v = acc[i][j];
                if (bias) v += bias[n];
                if (act == 1) v = 0.5f*v*(1.0f + erff(v*0.70710678118654752f));
                C[(size_t)m*N + n] = v;
            }
        }
    }
}

// ---------------- flash attention (online softmax) -----------------------
// 1 query per thread, 64 queries/block, DH=32 in registers.
// Q rows: b*TT + i ; K/V rows: b*lenK + j ; head columns h*32..h*32+31.
// causal=1: mask = (j <= i) && (tgt[b,j] != 0)   (CLS col j=0 always valid)
__global__ void __launch_bounds__(64)
k_flash(const float* __restrict__ Q, const float* __restrict__ Kp,
        const float* __restrict__ Vp, float* __restrict__ O,
        int lenK, int causal)
{
    __shared__ float Ks[64*32];
    __shared__ float Vs[64*32];
    __shared__ float pads[64];
    int bh = blockIdx.x;
    int b = bh / HH, h = bh % HH;
    int tid = threadIdx.x;                       // 0..63
    int i = blockIdx.y*64 + tid;                 // query index
    size_t qr = (size_t)(b*TT + i);

    const float scale = 0.17677669529663687f;    // 1/sqrt(32)
    float q[32];
    #pragma unroll
    for (int d = 0; d < 32; d++) q[d] = Q[qr*DD + h*32 + d] * scale;

    float m = -CUDART_INF_F, l = 0.0f, o[32];
    #pragma unroll
    for (int d = 0; d < 32; d++) o[d] = 0.0f;

    int nT = lenK / 64;
    if (causal) { int need = blockIdx.y + 1; if (need < nT) nT = need; }

    for (int tIdx = 0; tIdx < nT; tIdx++) {
        int j0 = tIdx*64;
        for (int idx = tid; idx < 512; idx += 64) {     // 512 float4s each
            int jj = idx >> 3, dq = (idx & 7) * 4;
            size_t row = (size_t)(b*lenK + j0 + jj);
            *(float4*)&Ks[jj*32 + dq] = *(const float4*)&Kp[row*DD + h*32 + dq];
            *(float4*)&Vs[jj*32 + dq] = *(const float4*)&Vp[row*DD + h*32 + dq];
        }
        if (causal) pads[tid] = g_padbuf[b*TT + j0 + tid];
        __syncthreads();

        #pragma unroll 1
        for (int jj = 0; jj < 64; jj++) {
            int j = j0 + jj;
            if (causal && (j > i || pads[jj] == 0.0f)) continue;
            const float* kr = &Ks[jj*32];
            float s = 0.0f;
            #pragma unroll
            for (int d = 0; d < 32; d++) s += q[d]*kr[d];
            float mn = fmaxf(m, s);
            float corr = __expf(m - mn);    // exp(-inf)=0 handles first hit
            float p = __expf(s - mn);
            l = l*corr + p;
            const float* vr = &Vs[jj*32];
            #pragma unroll
            for (int d = 0; d < 32; d++) o[d] = o[d]*corr + p*vr[d];
            m = mn;
        }
        __syncthreads();
    }
    float inv = 1.0f / l;
    #pragma unroll
    for (int d = 0; d < 32; d++) O[qr*DD + h*32 + d] = o[d]*inv;
}

// ---------------- fused residual-add + LayerNorm -------------------------
__global__ void k_addln(const float* __restrict__ X, const float* __restrict__ A,
                        const float* __restrict__ g, const float* __restrict__ be,
                        float* __restrict__ Y)
{
    int r = blockIdx.x, d = threadIdx.x;        // 256 threads
    float v = X[(size_t)r*DD + d] + A[(size_t)r*DD + d];
    __shared__ float sh[18];
    float s1 = v, s2 = v*v;
    #pragma unroll
    for (int off = 16; off; off >>= 1) {
        s1 += __shfl_down_sync(0xFFFFFFFFu, s1, off);
        s2 += __shfl_down_sync(0xFFFFFFFFu, s2, off);
    }
    int warp = d >> 5, lane = d & 31;
    if (lane == 0) { sh[warp] = s1; sh[8 + warp] = s2; }
    __syncthreads();
    if (d == 0) {
        float t1 = 0.f, t2 = 0.f;
        for (int w = 0; w < 8; w++) { t1 += sh[w]; t2 += sh[8 + w]; }
        float mean = t1 * (1.0f/256.0f);
        float var  = t2 * (1.0f/256.0f) - mean*mean;
        sh[16] = mean;
        sh[17] = rsqrtf(var + 1e-5f);
    }
    __syncthreads();
    Y[(size_t)r*DD + d] = (v - sh[16])*sh[17]*g[d] + be[d];
}

// ---------------- host orchestration -------------------------------------
extern "C" void kernel_launch(void* const* d_in, const int* in_sizes, int n_in,
                              void* d_out, int out_size)
{
    const int*   src   = (const int*)  d_in[0];
    const int*   tgt   = (const int*)  d_in[1];
    const float* enc   = (const float*)d_in[2];
    const float* emb   = (const float*)d_in[3];
    const float* Wq_s  = (const float*)d_in[4];
    const float* Wk_s  = (const float*)d_in[5];
    const float* Wv_s  = (const float*)d_in[6];
    const float* Wo_s  = (const float*)d_in[7];
    const float* bo_s  = (const float*)d_in[8];
    const float* Wq_c  = (const float*)d_in[9];
    const float* Wk_c  = (const float*)d_in[10];
    const float* Wv_c  = (const float*)d_in[11];
    const float* Wo_c  = (const float*)d_in[12];
    const float* bo_c  = (const float*)d_in[13];
    const float* W1    = (const float*)d_in[14];
    const float* b1    = (const float*)d_in[15];
    const float* W2    = (const float*)d_in[16];
    const float* b2    = (const float*)d_in[17];
    const float* g1    = (const float*)d_in[18];
    const float* be1   = (const float*)d_in[19];
    const float* g2    = (const float*)d_in[20];
    const float* be2   = (const float*)d_in[21];
    const float* g3    = (const float*)d_in[22];
    const float* be3   = (const float*)d_in[23];
    const float* Wf    = (const float*)d_in[24];
    const float* bf    = (const float*)d_in[25];
    float* out = (float*)d_out;

    float* s = nullptr;
    cudaGetSymbolAddress((void**)&s, g_scratch);
    float* x0   = s + O_X0;
    float* x1   = s + O_X1;
    float* x2   = s + O_X2;
    float* x3   = s + O_X3;
    float* q    = s + O_Q;
    float* k    = s + O_K;
    float* v    = s + O_V;
    float* att  = s + O_ATT;
    float* proj = s + O_PROJ;
    float* encz = s + O_ENCZ;
    float* ff   = s + O_FF;

    long long logitsN = (long long)BT * VOC;
    int write_ids = ((long long)out_size >= logitsN + BT);
    float* out_ids = out + logitsN;

    dim3 thr(16, 16);
    auto gg = [](int M, int N) { return dim3((unsigned)((N + 63) / 64), (unsigned)((M + 63) / 64)); };

    // embeddings + masks
    k_embed<<<BT, 256>>>(tgt, emb, out_ids, write_ids);
    k_encz <<<BB*SS, 256>>>(src, enc);

    // --- self attention ---
    k_gemm<<<gg(BT, DD), thr>>>(x0, Wq_s, nullptr, q, BT, DD, DD, 0);
    k_gemm<<<gg(BT, DD), thr>>>(x0, Wk_s, nullptr, k, BT, DD, DD, 0);
    k_gemm<<<gg(BT, DD), thr>>>(x0, Wv_s, nullptr, v, BT, DD, DD, 0);
    k_flash<<<dim3(BB*HH, TT/64), 64>>>(q, k, v, att, TT, 1);
    k_gemm<<<gg(BT, DD), thr>>>(att, Wo_s, bo_s, proj, BT, DD, DD, 0);
    k_addln<<<BT, 256>>>(x0, proj, g1, be1, x1);

    // --- cross attention ---
    k_gemm<<<gg(BT, DD), thr>>>(x1,   Wq_c, nullptr, q, BT, DD, DD, 0);
    k_gemm<<<gg(BB*SS, DD), thr>>>(encz, Wk_c, nullptr, k, BB*SS, DD, DD, 0);
    k_gemm<<<gg(BB*SS, DD), thr>>>(encz, Wv_c, nullptr, v, BB*SS, DD, DD, 0);
    k_flash<<<dim3(BB*HH, TT/64), 64>>>(q, k, v, att, SS, 0);
    k_gemm<<<gg(BT, DD), thr>>>(att, Wo_c, bo_c, proj, BT, DD, DD, 0);
    k_addln<<<BT, 256>>>(x1, proj, g2, be2, x2);

    // --- feed forward (exact-erf GELU fused into GEMM1 epilogue) ---
    k_gemm<<<gg(BT, FFD), thr>>>(x2, W1, b1, ff, BT, FFD, DD, 1);
    k_gemm<<<gg(BT, DD), thr>>>(ff, W2, b2, proj, BT, DD, FFD, 0);
    k_addln<<<BT, 256>>>(x2, proj, g3, be3, x3);

    // --- vocab projection straight into d_out ---
    k_gemm<<<gg(BT, VOC), thr>>>(x3, Wf, bf, out, BT, VOC, DD, 0);
}

// round 6
// speedup vs baseline: 2.3515x; 2.3515x over previous
#include <cuda_runtime.h>
#include <math.h>
#include <math_constants.h>
#include <stdint.h>

#define BB 2
#define TT 2048
#define SS 2048
#define DD 256
#define HH 8
#define DHH 32
#define FFD 2048
#define VOC 25426
#define BT (BB*TT)
#define QH (BB*HH*TT)
#define NSPLIT 4

// ---------------- scratch (no allocations allowed) ----------------
#define SLAB 1048576
#define O_X0   (0*SLAB)
#define O_X1   (1*SLAB)
#define O_X2   (2*SLAB)
#define O_X3   (3*SLAB)
#define O_Q    (4*SLAB)
#define O_K    (5*SLAB)
#define O_V    (6*SLAB)
#define O_ATT  (7*SLAB)
#define O_PROJ (8*SLAB)
#define O_ENCZ (9*SLAB)
#define O_FF   (10*SLAB)              // BT*FFD = 8 slabs
#define O_PO   (18*SLAB)              // NSPLIT*QH*32 = 4 slabs
#define O_PM   (22*SLAB)              // NSPLIT*QH
#define O_PL   (22*SLAB + 262144)
#define SCRATCH_FLOATS (23*SLAB)

__device__ float g_scratch[SCRATCH_FLOATS];
__device__ float g_padbuf[BT];

__device__ __forceinline__ uint32_t f2tf(float f) {
    uint32_t u; asm("cvt.rna.tf32.f32 %0, %1;" : "=r"(u) : "f"(f)); return u;
}
__device__ __forceinline__ float gelu_f(float v) {
    return 0.5f*v*(1.0f + erff(v*0.70710678118654752f));
}

// ---------------- embedding + positional encoding ----------------
__global__ void k_embed(const int* __restrict__ tgt_in,
                        const float* __restrict__ emb,
                        float* __restrict__ out_ids, int write_ids)
{
    int r = blockIdx.x;
    int d = threadIdx.x;
    int b = r / TT, t = r % TT;
    int id = (t == 0) ? VOC : tgt_in[b*(TT-1) + (t-1)];
    if (d == 0) {
        g_padbuf[r] = (id != 0) ? 1.0f : 0.0f;
        if (write_ids) out_ids[r] = (t == 0) ? 0.0f : (float)id;
    }
    int i2 = d & ~1;
    float div = __expf(-(float)i2 * (9.210340371976184f / 256.0f));
    float ang = (float)t * div;
    float pe  = (d & 1) ? cosf(ang) : sinf(ang);
    g_scratch[O_X0 + (size_t)r*DD + d] = 2.0f*emb[(size_t)id*DD + d] + pe;
}

__global__ void k_encz(const int* __restrict__ src, const float* __restrict__ enc)
{
    int r = blockIdx.x;
    int d = threadIdx.x;
    g_scratch[O_ENCZ + (size_t)r*DD + d] = (src[r] != 0) ? enc[(size_t)r*DD + d] : 0.0f;
}

// ---------------- TF32 tensor-core GEMM ----------------------------------
// C[M,N] = A[M,K] @ B[K,N] (+bias)(+gelu). 128x128x32 tile, 8 warps,
// warp tile 64x32 via mma.sync.m16n8k8.tf32. M%128==0, K%32==0. N guarded.
__global__ void __launch_bounds__(256)
k_mma(const float* __restrict__ A, const float* __restrict__ Bm,
      const float* __restrict__ bias, float* __restrict__ C,
      int M, int N, int K, int act)
{
    __shared__ uint32_t As[128][36];
    __shared__ uint32_t Bs[32][136];
    int tid = threadIdx.x;
    int lane = tid & 31, warp = tid >> 5;
    int wm0 = (warp >> 2) * 64, wn0 = (warp & 3) * 32;
    int m0 = blockIdx.y * 128, n0 = blockIdx.x * 128;

    float acc[4][4][4];
    #pragma unroll
    for (int i = 0; i < 4; i++)
        #pragma unroll
        for (int j = 0; j < 4; j++)
            #pragma unroll
            for (int r = 0; r < 4; r++) acc[i][j][r] = 0.0f;

    int ar = tid >> 3;            // 0..31
    int ac = (tid & 7) * 4;       // 0,4,..28
    int bc = tid & 127;           // 0..127
    int br0 = tid >> 7;           // 0..1

    for (int k0 = 0; k0 < K; k0 += 32) {
        #pragma unroll
        for (int p = 0; p < 4; p++) {
            int r = p*32 + ar;
            float4 v = *(const float4*)&A[(size_t)(m0 + r)*K + k0 + ac];
            uint4 u;
            u.x = f2tf(v.x); u.y = f2tf(v.y); u.z = f2tf(v.z); u.w = f2tf(v.w);
            *(uint4*)&As[r][ac] = u;
        }
        #pragma unroll
        for (int p = 0; p < 16; p++) {
            int r = p*2 + br0;
            int n = n0 + bc;
            float v = (n < N) ? Bm[(size_t)(k0 + r)*N + n] : 0.0f;
            Bs[r][bc] = f2tf(v);
        }
        __syncthreads();

        #pragma unroll
        for (int ks = 0; ks < 4; ks++) {
            uint32_t af[4][4], bf[4][2];
            int kk = ks*8 + (lane & 3);
            int rr = lane >> 2;
            #pragma unroll
            for (int mt = 0; mt < 4; mt++) {
                int r = wm0 + mt*16 + rr;
                af[mt][0] = As[r][kk];
                af[mt][1] = As[r+8][kk];
                af[mt][2] = As[r][kk+4];
                af[mt][3] = As[r+8][kk+4];
            }
            #pragma unroll
            for (int nt = 0; nt < 4; nt++) {
                int c = wn0 + nt*8 + rr;
                bf[nt][0] = Bs[kk][c];
                bf[nt][1] = Bs[kk+4][c];
            }
            #pragma unroll
            for (int mt = 0; mt < 4; mt++)
                #pragma unroll
                for (int nt = 0; nt < 4; nt++)
                    asm volatile(
                        "mma.sync.aligned.m16n8k8.row.col.f32.tf32.tf32.f32 "
                        "{%0,%1,%2,%3}, {%4,%5,%6,%7}, {%8,%9}, {%0,%1,%2,%3};"
                        : "+f"(acc[mt][nt][0]), "+f"(acc[mt][nt][1]),
                          "+f"(acc[mt][nt][2]), "+f"(acc[mt][nt][3])
                        : "r"(af[mt][0]), "r"(af[mt][1]),
                          "r"(af[mt][2]), "r"(af[mt][3]),
                          "r"(bf[nt][0]), "r"(bf[nt][1]));
        }
        __syncthreads();
    }

    #pragma unroll
    for (int mt = 0; mt < 4; mt++) {
        int row0 = m0 + wm0 + mt*16 + (lane >> 2);
        #pragma unroll
        for (int nt = 0; nt < 4; nt++) {
            int col = n0 + wn0 + nt*8 + 2*(lane & 3);
            #pragma unroll
            for (int h = 0; h < 2; h++) {
                int rw = row0 + h*8;
                float v0 = acc[mt][nt][h*2+0];
                float v1 = acc[mt][nt][h*2+1];
                if (col + 1 < N) {
                    if (bias) { v0 += bias[col]; v1 += bias[col+1]; }
                    if (act)  { v0 = gelu_f(v0); v1 = gelu_f(v1); }
                    float2 o; o.x = v0; o.y = v1;
                    *(float2*)&C[(size_t)rw*N + col] = o;
                } else if (col < N) {
                    if (bias) v0 += bias[col];
                    if (act)  v0 = gelu_f(v0);
                    C[(size_t)rw*N + col] = v0;
                }
            }
        }
    }
}

// ---------------- flash attention, KV-split, partials ---------------------
// grid (BB*HH, TT/64, NSPLIT), block 64. Writes un-normalized (m, l, o[32]).
__global__ void __launch_bounds__(64)
k_flash(const float* __restrict__ Q, const float* __restrict__ Kp,
        const float* __restrict__ Vp, int lenK, int causal)
{
    __shared__ float Ks[64*32];
    __shared__ float Vs[64*32];
    __shared__ float pads[64];
    int bh = blockIdx.x;
    int b = bh / HH, h = bh % HH;
    int tid = threadIdx.x;
    int i = blockIdx.y*64 + tid;
    size_t qr = (size_t)(b*TT + i);

    const float scale = 0.17677669529663687f;
    float q[32];
    #pragma unroll
    for (int d = 0; d < 32; d++) q[d] = Q[qr*DD + h*32 + d] * scale;

    float m = -CUDART_INF_F, l = 0.0f, o[32];
    #pragma unroll
    for (int d = 0; d < 32; d++) o[d] = 0.0f;

    int tilesTotal = lenK / 64;
    int tps = tilesTotal / NSPLIT;
    int t0 = blockIdx.z * tps, t1 = t0 + tps;
    if (causal) { int need = blockIdx.y + 1; if (t1 > need) t1 = need; }

    for (int tIdx = t0; tIdx < t1; tIdx++) {
        int j0 = tIdx*64;
        for (int idx = tid; idx < 512; idx += 64) {
            int jj = idx >> 3, dq = (idx & 7) * 4;
            size_t row = (size_t)(b*lenK + j0 + jj);
            *(float4*)&Ks[jj*32 + dq] = *(const float4*)&Kp[row*DD + h*32 + dq];
            *(float4*)&Vs[jj*32 + dq] = *(const float4*)&Vp[row*DD + h*32 + dq];
        }
        if (causal) pads[tid] = g_padbuf[b*TT + j0 + tid];
        __syncthreads();

        #pragma unroll 1
        for (int jj = 0; jj < 64; jj++) {
            int j = j0 + jj;
            if (causal && (j > i || pads[jj] == 0.0f)) continue;
            const float* kr = &Ks[jj*32];
            float s = 0.0f;
            #pragma unroll
            for (int d = 0; d < 32; d++) s += q[d]*kr[d];
            float mn = fmaxf(m, s);
            float corr = __expf(m - mn);
            float p = __expf(s - mn);
            l = l*corr + p;
            const float* vr = &Vs[jj*32];
            #pragma unroll
            for (int d = 0; d < 32; d++) o[d] = o[d]*corr + p*vr[d];
            m = mn;
        }
        __syncthreads();
    }

    size_t base = (size_t)blockIdx.z*QH + (size_t)bh*TT + i;
    g_scratch[O_PM + base] = m;
    g_scratch[O_PL + base] = l;
    #pragma unroll
    for (int d = 0; d < 32; d++)
        g_scratch[O_PO + base*32 + d] = o[d];
}

// merge NSPLIT partials -> attention output [BT, DD]
__global__ void k_fmerge(float* __restrict__ O)
{
    int idx = blockIdx.x*256 + threadIdx.x;   // qh*32 + d
    int qh = idx >> 5, d = idx & 31;
    float M = -CUDART_INF_F;
    #pragma unroll
    for (int s = 0; s < NSPLIT; s++)
        M = fmaxf(M, g_scratch[O_PM + (size_t)s*QH + qh]);
    float L = 0.0f, acc = 0.0f;
    #pragma unroll
    for (int s = 0; s < NSPLIT; s++) {
        size_t base = (size_t)s*QH + qh;
        float w = __expf(g_scratch[O_PM + base] - M);
        L   += w * g_scratch[O_PL + base];
        acc += w * g_scratch[O_PO + base*32 + d];
    }
    int bh = qh / TT, i = qh % TT;
    int b = bh / HH, h = bh % HH;
    O[(size_t)(b*TT + i)*DD + h*32 + d] = acc / L;
}

// ---------------- fused residual-add + LayerNorm -------------------------
__global__ void k_addln(const float* __restrict__ X, const float* __restrict__ A,
                        const float* __restrict__ g, const float* __restrict__ be,
                        float* __restrict__ Y)
{
    int r = blockIdx.x, d = threadIdx.x;
    float v = X[(size_t)r*DD + d] + A[(size_t)r*DD + d];
    __shared__ float sh[18];
    float s1 = v, s2 = v*v;
    #pragma unroll
    for (int off = 16; off; off >>= 1) {
        s1 += __shfl_down_sync(0xFFFFFFFFu, s1, off);
        s2 += __shfl_down_sync(0xFFFFFFFFu, s2, off);
    }
    int warp = d >> 5, lane = d & 31;
    if (lane == 0) { sh[warp] = s1; sh[8 + warp] = s2; }
    __syncthreads();
    if (d == 0) {
        float t1 = 0.f, t2 = 0.f;
        for (int w = 0; w < 8; w++) { t1 += sh[w]; t2 += sh[8 + w]; }
        float mean = t1 * (1.0f/256.0f);
        float var  = t2 * (1.0f/256.0f) - mean*mean;
        sh[16] = mean;
        sh[17] = rsqrtf(var + 1e-5f);
    }
    __syncthreads();
    Y[(size_t)r*DD + d] = (v - sh[16])*sh[17]*g[d] + be[d];
}

// ---------------- host orchestration -------------------------------------
extern "C" void kernel_launch(void* const* d_in, const int* in_sizes, int n_in,
                              void* d_out, int out_size)
{
    const int*   src   = (const int*)  d_in[0];
    const int*   tgt   = (const int*)  d_in[1];
    const float* enc   = (const float*)d_in[2];
    const float* emb   = (const float*)d_in[3];
    const float* Wq_s  = (const float*)d_in[4];
    const float* Wk_s  = (const float*)d_in[5];
    const float* Wv_s  = (const float*)d_in[6];
    const float* Wo_s  = (const float*)d_in[7];
    const float* bo_s  = (const float*)d_in[8];
    const float* Wq_c  = (const float*)d_in[9];
    const float* Wk_c  = (const float*)d_in[10];
    const float* Wv_c  = (const float*)d_in[11];
    const float* Wo_c  = (const float*)d_in[12];
    const float* bo_c  = (const float*)d_in[13];
    const float* W1    = (const float*)d_in[14];
    const float* b1    = (const float*)d_in[15];
    const float* W2    = (const float*)d_in[16];
    const float* b2    = (const float*)d_in[17];
    const float* g1    = (const float*)d_in[18];
    const float* be1   = (const float*)d_in[19];
    const float* g2    = (const float*)d_in[20];
    const float* be2   = (const float*)d_in[21];
    const float* g3    = (const float*)d_in[22];
    const float* be3   = (const float*)d_in[23];
    const float* Wf    = (const float*)d_in[24];
    const float* bf    = (const float*)d_in[25];
    float* out = (float*)d_out;

    float* s = nullptr;
    cudaGetSymbolAddress((void**)&s, g_scratch);
    float* x0   = s + O_X0;
    float* x1   = s + O_X1;
    float* x2   = s + O_X2;
    float* x3   = s + O_X3;
    float* q    = s + O_Q;
    float* k    = s + O_K;
    float* v    = s + O_V;
    float* att  = s + O_ATT;
    float* proj = s + O_PROJ;
    float* encz = s + O_ENCZ;
    float* ff   = s + O_FF;

    long long logitsN = (long long)BT * VOC;
    int write_ids = ((long long)out_size >= logitsN + BT);
    float* out_ids = out + logitsN;

    auto gg = [](int M, int N) { return dim3((unsigned)((N + 127) / 128), (unsigned)(M / 128)); };

    k_embed<<<BT, 256>>>(tgt, emb, out_ids, write_ids);
    k_encz <<<BB*SS, 256>>>(src, enc);

    // --- self attention ---
    k_mma<<<gg(BT, DD), 256>>>(x0, Wq_s, nullptr, q, BT, DD, DD, 0);
    k_mma<<<gg(BT, DD), 256>>>(x0, Wk_s, nullptr, k, BT, DD, DD, 0);
    k_mma<<<gg(BT, DD), 256>>>(x0, Wv_s, nullptr, v, BT, DD, DD, 0);
    k_flash<<<dim3(BB*HH, TT/64, NSPLIT), 64>>>(q, k, v, TT, 1);
    k_fmerge<<<QH*32/256, 256>>>(att);
    k_mma<<<gg(BT, DD), 256>>>(att, Wo_s, bo_s, proj, BT, DD, DD, 0);
    k_addln<<<BT, 256>>>(x0, proj, g1, be1, x1);

    // --- cross attention ---
    k_mma<<<gg(BT, DD), 256>>>(x1,   Wq_c, nullptr, q, BT, DD, DD, 0);
    k_mma<<<gg(BB*SS, DD), 256>>>(encz, Wk_c, nullptr, k, BB*SS, DD, DD, 0);
    k_mma<<<gg(BB*SS, DD), 256>>>(encz, Wv_c, nullptr, v, BB*SS, DD, DD, 0);
    k_flash<<<dim3(BB*HH, TT/64, NSPLIT), 64>>>(q, k, v, SS, 0);
    k_fmerge<<<QH*32/256, 256>>>(att);
    k_mma<<<gg(BT, DD), 256>>>(att, Wo_c, bo_c, proj, BT, DD, DD, 0);
    k_addln<<<BT, 256>>>(x1, proj, g2, be2, x2);

    // --- feed forward ---
    k_mma<<<gg(BT, FFD), 256>>>(x2, W1, b1, ff, BT, FFD, DD, 1);
    k_mma<<<gg(BT, DD), 256>>>(ff, W2, b2, proj, BT, DD, FFD, 0);
    k_addln<<<BT, 256>>>(x2, proj, g3, be3, x3);

    // --- vocab projection straight into d_out ---
    k_mma<<<gg(BT, VOC), 256>>>(x3, Wf, bf, out, BT, VOC, DD, 0);
}

// round 7
// speedup vs baseline: 2.7759x; 1.1805x over previous
#include <cuda_runtime.h>
#include <math.h>
#include <math_constants.h>
#include <stdint.h>

#define BB 2
#define TT 2048
#define SS 2048
#define DD 256
#define HH 8
#define FFD 2048
#define VOC 25426
#define VOCP 25472              // padded vocab (199*128, mult of 16)
#define BT (BB*TT)
#define QH (BB*HH*TT)
#define NSPLIT 8

// ---------------- scratch ----------------
#define SLAB 1048576
#define O_X0   (0*SLAB)
#define O_X1   (1*SLAB)
#define O_X2   (2*SLAB)
#define O_X3   (3*SLAB)
#define O_Q    (4*SLAB)
#define O_K    (5*SLAB)
#define O_V    (6*SLAB)
#define O_ATT  (7*SLAB)
#define O_PROJ (8*SLAB)
#define O_ENCZ (9*SLAB)
#define O_FF   ((size_t)10*SLAB)                 // 8 slabs
#define O_PO   ((size_t)18*SLAB)                 // NSPLIT*QH*32 = 8 slabs
#define O_PM   ((size_t)26*SLAB)
#define O_PL   ((size_t)26*SLAB + NSPLIT*QH)
#define O_WATT ((size_t)27*SLAB)                 // 8 x 65536
#define O_W1   (O_WATT + 8*65536)
#define O_W2   (O_W1 + 524288)
#define O_WF   (O_W2 + 524288)                   // 256*25472
#define SCRATCH_FLOATS ((size_t)35*SLAB)

__device__ float g_scratch[SCRATCH_FLOATS];
__device__ float g_padbuf[BT];

__device__ __forceinline__ uint32_t f2tf(float f) {
    uint32_t u; asm("cvt.rna.tf32.f32 %0, %1;" : "=r"(u) : "f"(f)); return u;
}
__device__ __forceinline__ float tfr(float f) { return __uint_as_float(f2tf(f)); }
__device__ __forceinline__ float gelu_f(float v) {
    return 0.5f*v*(1.0f + erff(v*0.70710678118654752f));
}
__device__ __forceinline__ void cp16(uint32_t dst, const void* src) {
    asm volatile("cp.async.cg.shared.global [%0], [%1], 16;" :: "r"(dst), "l"(src));
}

// ---------------- weight pre-conversion (RNA tf32) ----------------
__global__ void k_conv(const float* __restrict__ src, float* __restrict__ dst, int n)
{
    int i = blockIdx.x*256 + threadIdx.x;
    if (i < n) dst[i] = tfr(src[i]);
}
__global__ void k_prep8(const float* w0, const float* w1, const float* w2, const float* w3,
                        const float* w4, const float* w5, const float* w6, const float* w7)
{
    int idx = blockIdx.x*256 + threadIdx.x;       // 0..524287
    int w = idx >> 16, r = idx & 65535;
    const float* src;
    switch (w) {
        case 0: src = w0; break; case 1: src = w1; break;
        case 2: src = w2; break; case 3: src = w3; break;
        case 4: src = w4; break; case 5: src = w5; break;
        case 6: src = w6; break; default: src = w7; break;
    }
    g_scratch[O_WATT + (size_t)w*65536 + r] = tfr(src[r]);
}
__global__ void k_convpad(const float* __restrict__ src)   // Wf -> padded
{
    size_t idx = (size_t)blockIdx.x*256 + threadIdx.x;     // 256*25472 total
    int k = (int)(idx / VOCP), n = (int)(idx % VOCP);
    g_scratch[O_WF + idx] = (n < VOC) ? tfr(src[(size_t)k*VOC + n]) : 0.0f;
}

// ---------------- embedding + positional encoding ----------------
__global__ void k_embed(const int* __restrict__ tgt_in,
                        const float* __restrict__ emb,
                        float* __restrict__ out_ids, int write_ids)
{
    int r = blockIdx.x;
    int d = threadIdx.x;
    int b = r / TT, t = r % TT;
    int id = (t == 0) ? VOC : tgt_in[b*(TT-1) + (t-1)];
    if (d == 0) {
        g_padbuf[r] = (id != 0) ? 1.0f : 0.0f;
        if (write_ids) out_ids[r] = (t == 0) ? 0.0f : (float)id;
    }
    int i2 = d & ~1;
    float div = __expf(-(float)i2 * (9.210340371976184f / 256.0f));
    float ang = (float)t * div;
    float pe  = (d & 1) ? cosf(ang) : sinf(ang);
    g_scratch[O_X0 + (size_t)r*DD + d] = tfr(2.0f*emb[(size_t)id*DD + d] + pe);
}

__global__ void k_encz(const int* __restrict__ src, const float* __restrict__ enc)
{
    int r = blockIdx.x;
    int d = threadIdx.x;
    g_scratch[O_ENCZ + (size_t)r*DD + d] = (src[r] != 0) ? tfr(enc[(size_t)r*DD + d]) : 0.0f;
}

// ---------------- pipelined TF32 GEMM core --------------------------------
// C[M,N] = A[M,K] @ B[K,N](ldb) (+bias)(+gelu)(+tf32-round). Both operands
// must already be tf32-exact fp32. 128x128x32 CTA tile, 8 warps (2x4),
// cp.async double buffer, ldmatrix A frags, padded B smem. M%128, K%32 == 0.
// smem: A 2x(128x32) @ SW128 swizzle, B 2x(32x136) padded. 67584 bytes.
#define SMEM_GEMM_BYTES ((2*128*32 + 2*32*136)*4)

__device__ __forceinline__ void gemm128(
    const float* __restrict__ A, const float* __restrict__ Bm,
    const float* __restrict__ bias, float* __restrict__ C,
    int M, int N, int K, int ldb, int act, int roundOut, uint32_t* sh)
{
    uint32_t* BsW = sh + 8192;                        // B words base
    uint32_t shA = (uint32_t)__cvta_generic_to_shared(sh);
    uint32_t shB = (uint32_t)__cvta_generic_to_shared(sh + 8192);

    int tid = threadIdx.x;
    int lane = tid & 31, warp = tid >> 5;
    int wm0 = (warp >> 2) * 64, wn0 = (warp & 3) * 32;
    int m0 = blockIdx.y * 128, n0 = blockIdx.x * 128;

    // cp.async source/dest precompute
    int ar  = tid >> 3, ac16 = tid & 7;               // A: rows ar+32i, chunk ac16
    const float* srcA0 = A + (size_t)(m0 + ar)*K + ac16*4;
    uint32_t dstA0 = shA + (uint32_t)((ar*32 + ((ac16 ^ (ar & 7)) << 2)) << 2);
    int br  = tid >> 5, bc = tid & 31;                // B: rows br+8i, chunk bc
    const float* srcB0 = Bm + (size_t)br*ldb + n0 + bc*4;
    uint32_t dstB0 = shB + (uint32_t)((br*136 + bc*4) << 2);

    // ldmatrix per-lane A address precompute
    int arow  = (lane & 7) | (lane & 8);
    int khalf = lane >> 4;
    int sw    = lane & 7;
    uint32_t baseA = shA + (uint32_t)(((wm0 + arow)*32) << 2);

    // B fragment word base
    int baseB = (lane & 3)*136 + wn0 + (lane >> 2);

    float acc[4][4][4];
    #pragma unroll
    for (int i = 0; i < 4; i++)
        #pragma unroll
        for (int j = 0; j < 4; j++) {
            acc[i][j][0]=0.f; acc[i][j][1]=0.f; acc[i][j][2]=0.f; acc[i][j][3]=0.f;
        }

    int nk = K >> 5;

    // prologue: load tile 0 into buffer 0
    #pragma unroll
    for (int i = 0; i < 4; i++)
        cp16(dstA0 + i*4096u, srcA0 + (size_t)i*32*K);
    #pragma unroll
    for (int i = 0; i < 4; i++)
        cp16(dstB0 + i*4352u, srcB0 + (size_t)i*8*ldb);
    asm volatile("cp.async.commit_group;");
    asm volatile("cp.async.wait_group 0;");
    __syncthreads();

    for (int kt = 0; kt < nk; kt++) {
        int cur = kt & 1;
        if (kt + 1 < nk) {                            // prefetch next tile
            int k0 = (kt + 1) << 5;
            uint32_t abuf = dstA0 + (cur ^ 1)*16384u;
            const float* asrc = srcA0 + k0;
            #pragma unroll
            for (int i = 0; i < 4; i++)
                cp16(abuf + i*4096u, asrc + (size_t)i*32*K);
            uint32_t bbuf = dstB0 + (cur ^ 1)*17408u;
            const float* bsrc = srcB0 + (size_t)k0*ldb;
            #pragma unroll
            for (int i = 0; i < 4; i++)
                cp16(bbuf + i*4352u, bsrc + (size_t)i*8*ldb);
            asm volatile("cp.async.commit_group;");
        }

        uint32_t aB = baseA + cur*16384u;
        const uint32_t* bW = BsW + cur*4352 + baseB;

        #pragma unroll
        for (int ks = 0; ks < 4; ks++) {
            uint32_t af[4][4], bfr[4][2];
            uint32_t csw = (uint32_t)((((ks*2 + khalf) ^ sw) << 4));
            #pragma unroll
            for (int mt = 0; mt < 4; mt++) {
                uint32_t addr = aB + mt*2048u + csw;
                asm volatile(
                    "ldmatrix.sync.aligned.m8n8.x4.shared.b16 {%0,%1,%2,%3}, [%4];"
                    : "=r"(af[mt][0]), "=r"(af[mt][1]), "=r"(af[mt][2]), "=r"(af[mt][3])
                    : "r"(addr));
            }
            #pragma unroll
            for (int nt = 0; nt < 4; nt++) {
                bfr[nt][0] = bW[ks*1088 + nt*8];
                bfr[nt][1] = bW[ks*1088 + 544 + nt*8];
            }
            #pragma unroll
            for (int mt = 0; mt < 4; mt++)
                #pragma unroll
                for (int nt = 0; nt < 4; nt++)
                    asm volatile(
                        "mma.sync.aligned.m16n8k8.row.col.f32.tf32.tf32.f32 "
                        "{%0,%1,%2,%3}, {%4,%5,%6,%7}, {%8,%9}, {%0,%1,%2,%3};"
                        : "+f"(acc[mt][nt][0]), "+f"(acc[mt][nt][1]),
                          "+f"(acc[mt][nt][2]), "+f"(acc[mt][nt][3])
                        : "r"(af[mt][0]), "r"(af[mt][1]),
                          "r"(af[mt][2]), "r"(af[mt][3]),
                          "r"(bfr[nt][0]), "r"(bfr[nt][1]));
        }

        if (kt + 1 < nk) {
            asm volatile("cp.async.wait_group 0;");
            __syncthreads();
        }
    }

    #pragma unroll
    for (int mt = 0; mt < 4; mt++) {
        int row0 = m0 + wm0 + mt*16 + (lane >> 2);
        #pragma unroll
        for (int nt = 0; nt < 4; nt++) {
            int col = n0 + wn0 + nt*8 + 2*(lane & 3);
            #pragma unroll
            for (int h = 0; h < 2; h++) {
                int rw = row0 + h*8;
                float v0 = acc[mt][nt][h*2+0];
                float v1 = acc[mt][nt][h*2+1];
                if (col + 1 < N) {
                    if (bias) { v0 += bias[col]; v1 += bias[col+1]; }
                    if (act)  { v0 = gelu_f(v0); v1 = gelu_f(v1); }
                    if (roundOut) { v0 = tfr(v0); v1 = tfr(v1); }
                    float2 o; o.x = v0; o.y = v1;
                    *(float2*)&C[(size_t)rw*N + col] = o;
                } else if (col < N) {
                    if (bias) v0 += bias[col];
                    if (act)  v0 = gelu_f(v0);
                    if (roundOut) v0 = tfr(v0);
                    C[(size_t)rw*N + col] = v0;
                }
            }
        }
    }
}

__global__ void __launch_bounds__(256)
k_mma(const float* __restrict__ A, const float* __restrict__ Bm,
      const float* __restrict__ bias, float* __restrict__ C,
      int M, int N, int K, int ldb, int act, int roundOut)
{
    extern __shared__ uint32_t sh[];
    gemm128(A, Bm, bias, C, M, N, K, ldb, act, roundOut, sh);
}

// fused triple GEMM: blockIdx.z selects (A, W, C) set. N=K=256, no bias.
__global__ void __launch_bounds__(256)
k_mma3(const float* a0, const float* a1, const float* a2,
       const float* w0, const float* w1, const float* w2,
       float* c0, float* c1, float* c2, int M)
{
    extern __shared__ uint32_t sh[];
    const float* A; const float* W; float* C;
    if (blockIdx.z == 0)      { A = a0; W = w0; C = c0; }
    else if (blockIdx.z == 1) { A = a1; W = w1; C = c1; }
    else                      { A = a2; W = w2; C = c2; }
    gemm128(A, W, nullptr, C, M, DD, DD, DD, 0, 0, sh);
}

// ---------------- flash attention, KV-split ---------------------
__global__ void __launch_bounds__(64)
k_flash(const float* __restrict__ Q, const float* __restrict__ Kp,
        const float* __restrict__ Vp, int lenK, int causal)
{
    __shared__ float Ks[64*32];
    __shared__ float Vs[64*32];
    __shared__ float pads[64];
    int bh = blockIdx.x;
    int b = bh / HH, h = bh % HH;
    int tid = threadIdx.x;
    int i = blockIdx.y*64 + tid;
    size_t qr = (size_t)(b*TT + i);

    const float scale = 0.17677669529663687f;
    float q[32];
    #pragma unroll
    for (int d = 0; d < 32; d++) q[d] = Q[qr*DD + h*32 + d] * scale;

    float m = -CUDART_INF_F, l = 0.0f, o[32];
    #pragma unroll
    for (int d = 0; d < 32; d++) o[d] = 0.0f;

    int tilesTotal = lenK / 64;
    int tps = tilesTotal / NSPLIT;
    int t0 = blockIdx.z * tps, t1 = t0 + tps;
    if (causal) { int need = blockIdx.y + 1; if (t1 > need) t1 = need; }

    for (int tIdx = t0; tIdx < t1; tIdx++) {
        int j0 = tIdx*64;
        for (int idx = tid; idx < 512; idx += 64) {
            int jj = idx >> 3, dq = (idx & 7) * 4;
            size_t row = (size_t)(b*lenK + j0 + jj);
            *(float4*)&Ks[jj*32 + dq] = *(const float4*)&Kp[row*DD + h*32 + dq];
            *(float4*)&Vs[jj*32 + dq] = *(const float4*)&Vp[row*DD + h*32 + dq];
        }
        if (causal) pads[tid] = g_padbuf[b*TT + j0 + tid];
        __syncthreads();

        #pragma unroll 1
        for (int jj = 0; jj < 64; jj++) {
            int j = j0 + jj;
            if (causal && (j > i || pads[jj] == 0.0f)) continue;
            const float* kr = &Ks[jj*32];
            float s = 0.0f;
            #pragma unroll
            for (int d = 0; d < 32; d++) s += q[d]*kr[d];
            float mn = fmaxf(m, s);
            float corr = __expf(m - mn);
            float p = __expf(s - mn);
            l = l*corr + p;
            const float* vr = &Vs[jj*32];
            #pragma unroll
            for (int d = 0; d < 32; d++) o[d] = o[d]*corr + p*vr[d];
            m = mn;
        }
        __syncthreads();
    }

    size_t base = (size_t)blockIdx.z*QH + (size_t)bh*TT + i;
    g_scratch[O_PM + base] = m;
    g_scratch[O_PL + base] = l;
    #pragma unroll
    for (int d = 0; d < 32; d++)
        g_scratch[O_PO + base*32 + d] = o[d];
}

__global__ void k_fmerge(float* __restrict__ O)
{
    int idx = blockIdx.x*256 + threadIdx.x;
    int qh = idx >> 5, d = idx & 31;
    float M = -CUDART_INF_F;
    #pragma unroll
    for (int s = 0; s < NSPLIT; s++)
        M = fmaxf(M, g_scratch[O_PM + (size_t)s*QH + qh]);
    float L = 0.0f, acc = 0.0f;
    #pragma unroll
    for (int s = 0; s < NSPLIT; s++) {
        size_t base = (size_t)s*QH + qh;
        float w = __expf(g_scratch[O_PM + base] - M);
        L   += w * g_scratch[O_PL + base];
        acc += w * g_scratch[O_PO + base*32 + d];
    }
    int bh = qh / TT, i = qh % TT;
    int b = bh / HH, h = bh % HH;
    O[(size_t)(b*TT + i)*DD + h*32 + d] = tfr(acc / L);
}

// ---------------- fused residual-add + LayerNorm -------------------------
__global__ void k_addln(const float* __restrict__ X, const float* __restrict__ A,
                        const float* __restrict__ g, const float* __restrict__ be,
                        float* __restrict__ Y)
{
    int r = blockIdx.x, d = threadIdx.x;
    float v = X[(size_t)r*DD + d] + A[(size_t)r*DD + d];
    __shared__ float sh[18];
    float s1 = v, s2 = v*v;
    #pragma unroll
    for (int off = 16; off; off >>= 1) {
        s1 += __shfl_down_sync(0xFFFFFFFFu, s1, off);
        s2 += __shfl_down_sync(0xFFFFFFFFu, s2, off);
    }
    int warp = d >> 5, lane = d & 31;
    if (lane == 0) { sh[warp] = s1; sh[8 + warp] = s2; }
    __syncthreads();
    if (d == 0) {
        float t1 = 0.f, t2 = 0.f;
        for (int w = 0; w < 8; w++) { t1 += sh[w]; t2 += sh[8 + w]; }
        float mean = t1 * (1.0f/256.0f);
        float var  = t2 * (1.0f/256.0f) - mean*mean;
        sh[16] = mean;
        sh[17] = rsqrtf(var + 1e-5f);
    }
    __syncthreads();
    Y[(size_t)r*DD + d] = tfr((v - sh[16])*sh[17]*g[d] + be[d]);
}

// ---------------- host orchestration -------------------------------------
extern "C" void kernel_launch(void* const* d_in, const int* in_sizes, int n_in,
                              void* d_out, int out_size)
{
    const int*   src   = (const int*)  d_in[0];
    const int*   tgt   = (const int*)  d_in[1];
    const float* enc   = (const float*)d_in[2];
    const float* emb   = (const float*)d_in[3];
    const float* Wq_s  = (const float*)d_in[4];
    const float* Wk_s  = (const float*)d_in[5];
    const float* Wv_s  = (const float*)d_in[6];
    const float* Wo_s  = (const float*)d_in[7];
    const float* bo_s  = (const float*)d_in[8];
    const float* Wq_c  = (const float*)d_in[9];
    const float* Wk_c  = (const float*)d_in[10];
    const float* Wv_c  = (const float*)d_in[11];
    const float* Wo_c  = (const float*)d_in[12];
    const float* bo_c  = (const float*)d_in[13];
    const float* W1    = (const float*)d_in[14];
    const float* b1    = (const float*)d_in[15];
    const float* W2    = (const float*)d_in[16];
    const float* b2    = (const float*)d_in[17];
    const float* g1    = (const float*)d_in[18];
    const float* be1   = (const float*)d_in[19];
    const float* g2    = (const float*)d_in[20];
    const float* be2   = (const float*)d_in[21];
    const float* g3    = (const float*)d_in[22];
    const float* be3   = (const float*)d_in[23];
    const float* Wf    = (const float*)d_in[24];
    const float* bf    = (const float*)d_in[25];
    float* out = (float*)d_out;

    float* s = nullptr;
    cudaGetSymbolAddress((void**)&s, g_scratch);
    float* x0   = s + O_X0;
    float* x1   = s + O_X1;
    float* x2   = s + O_X2;
    float* x3   = s + O_X3;
    float* q    = s + O_Q;
    float* k    = s + O_K;
    float* v    = s + O_V;
    float* att  = s + O_ATT;
    float* proj = s + O_PROJ;
    float* encz = s + O_ENCZ;
    float* ff   = s + O_FF;
    float* wqs  = s + O_WATT + 0*65536;
    float* wks  = s + O_WATT + 1*65536;
    float* wvs  = s + O_WATT + 2*65536;
    float* wos  = s + O_WATT + 3*65536;
    float* wqc  = s + O_WATT + 4*65536;
    float* wkc  = s + O_WATT + 5*65536;
    float* wvc  = s + O_WATT + 6*65536;
    float* woc  = s + O_WATT + 7*65536;
    float* w1c  = s + O_W1;
    float* w2c  = s + O_W2;
    float* wfc  = s + O_WF;

    long long logitsN = (long long)BT * VOC;
    int write_ids = ((long long)out_size >= logitsN + BT);
    float* out_ids = out + logitsN;

    cudaFuncSetAttribute(k_mma,  cudaFuncAttributeMaxDynamicSharedMemorySize, SMEM_GEMM_BYTES);
    cudaFuncSetAttribute(k_mma3, cudaFuncAttributeMaxDynamicSharedMemorySize, SMEM_GEMM_BYTES);

    auto gg = [](int M, int N) { return dim3((unsigned)((N + 127) / 128), (unsigned)(M / 128)); };

    // weight prep (tf32 RNA) + embeddings
    k_prep8<<<2048, 256>>>(Wq_s, Wk_s, Wv_s, Wo_s, Wq_c, Wk_c, Wv_c, Wo_c);
    k_conv<<<2048, 256>>>(W1, w1c, 524288);
    k_conv<<<2048, 256>>>(W2, w2c, 524288);
    k_convpad<<<VOCP, 256>>>(Wf);
    k_embed<<<BT, 256>>>(tgt, emb, out_ids, write_ids);
    k_encz <<<BB*SS, 256>>>(src, enc);

    // --- self attention ---
    k_mma3<<<dim3(2, 32, 3), 256, SMEM_GEMM_BYTES>>>(x0, x0, x0, wqs, wks, wvs, q, k, v, BT);
    k_flash<<<dim3(BB*HH, TT/64, NSPLIT), 64>>>(q, k, v, TT, 1);
    k_fmerge<<<QH*32/256, 256>>>(att);
    k_mma<<<gg(BT, DD), 256, SMEM_GEMM_BYTES>>>(att, wos, bo_s, proj, BT, DD, DD, DD, 0, 0);
    k_addln<<<BT, 256>>>(x0, proj, g1, be1, x1);

    // --- cross attention ---
    k_mma3<<<dim3(2, 32, 3), 256, SMEM_GEMM_BYTES>>>(x1, encz, encz, wqc, wkc, wvc, q, k, v, BT);
    k_flash<<<dim3(BB*HH, TT/64, NSPLIT), 64>>>(q, k, v, SS, 0);
    k_fmerge<<<QH*32/256, 256>>>(att);
    k_mma<<<gg(BT, DD), 256, SMEM_GEMM_BYTES>>>(att, woc, bo_c, proj, BT, DD, DD, DD, 0, 0);
    k_addln<<<BT, 256>>>(x1, proj, g2, be2, x2);

    // --- feed forward ---
    k_mma<<<gg(BT, FFD), 256, SMEM_GEMM_BYTES>>>(x2, w1c, b1, ff, BT, FFD, DD, FFD, 1, 1);
    k_mma<<<gg(BT, DD), 256, SMEM_GEMM_BYTES>>>(ff, w2c, b2, proj, BT, DD, FFD, DD, 0, 0);
    k_addln<<<BT, 256>>>(x2, proj, g3, be3, x3);

    // --- vocab projection into d_out ---
    k_mma<<<gg(BT, VOC), 256, SMEM_GEMM_BYTES>>>(x3, wfc, bf, out, BT, VOC, DD, VOCP, 0, 0);
}